// round 2
// baseline (speedup 1.0000x reference)
#include <cuda_runtime.h>
#include <math.h>

// Problem constants
#define BT    8192     // B*T
#define TSEQ  512
#define NHQ   8
#define NKVH  4
#define DH    128

// Scratch (device globals: allocation-free contract)
__device__ float g_Q [BT * 1024];
__device__ float g_K [BT * 512];
__device__ float g_V [BT * 512];
__device__ float g_AO[BT * 1024];

// ---------------------------------------------------------------------------
// SGEMM: C[M,N] = A[M,K] @ B[K,N], row-major, M%128==0, N%128==0, K%8==0
// BM=BN=128, BK=8, 256 threads, 8x8 microtile per thread.
// ---------------------------------------------------------------------------
__global__ __launch_bounds__(256) void sgemm128(const float* __restrict__ A,
                                                const float* __restrict__ B,
                                                float* __restrict__ C,
                                                int M, int N, int K) {
    __shared__ float As[8][128];   // transposed: As[k][m]
    __shared__ float Bs[8][128];   // Bs[k][n]
    const int t  = threadIdx.x;
    const int tx = t & 15;
    const int ty = t >> 4;
    const int row0 = blockIdx.y * 128;
    const int col0 = blockIdx.x * 128;

    float acc[8][8];
#pragma unroll
    for (int i = 0; i < 8; i++)
#pragma unroll
        for (int j = 0; j < 8; j++) acc[i][j] = 0.f;

    const int ar = t >> 1;          // 0..127
    const int ac = (t & 1) * 4;     // 0 or 4
    const int br = t >> 5;          // 0..7
    const int bc = (t & 31) * 4;    // 0..124

    for (int k0 = 0; k0 < K; k0 += 8) {
        float4 av = *reinterpret_cast<const float4*>(&A[(size_t)(row0 + ar) * K + k0 + ac]);
        float4 bv = *reinterpret_cast<const float4*>(&B[(size_t)(k0 + br) * N + col0 + bc]);
        As[ac + 0][ar] = av.x;
        As[ac + 1][ar] = av.y;
        As[ac + 2][ar] = av.z;
        As[ac + 3][ar] = av.w;
        *reinterpret_cast<float4*>(&Bs[br][bc]) = bv;
        __syncthreads();
#pragma unroll
        for (int k = 0; k < 8; k++) {
            float4 a0 = *reinterpret_cast<float4*>(&As[k][ty * 8]);
            float4 a1 = *reinterpret_cast<float4*>(&As[k][ty * 8 + 4]);
            float4 b0 = *reinterpret_cast<float4*>(&Bs[k][tx * 8]);
            float4 b1 = *reinterpret_cast<float4*>(&Bs[k][tx * 8 + 4]);
            float a[8] = {a0.x, a0.y, a0.z, a0.w, a1.x, a1.y, a1.z, a1.w};
            float b[8] = {b0.x, b0.y, b0.z, b0.w, b1.x, b1.y, b1.z, b1.w};
#pragma unroll
            for (int i = 0; i < 8; i++)
#pragma unroll
                for (int j = 0; j < 8; j++)
                    acc[i][j] += a[i] * b[j];
        }
        __syncthreads();
    }
#pragma unroll
    for (int i = 0; i < 8; i++) {
        float4 c0 = make_float4(acc[i][0], acc[i][1], acc[i][2], acc[i][3]);
        float4 c1 = make_float4(acc[i][4], acc[i][5], acc[i][6], acc[i][7]);
        size_t off = (size_t)(row0 + ty * 8 + i) * N + col0 + tx * 8;
        *reinterpret_cast<float4*>(&C[off])     = c0;
        *reinterpret_cast<float4*>(&C[off + 4]) = c1;
    }
}

// ---------------------------------------------------------------------------
// RoPE, in place on X[BT, nh*128]. One thread per (row, head, i<64) pair.
// ---------------------------------------------------------------------------
__global__ void rope_kernel(float* __restrict__ X, int nh, int total) {
    int idx = blockIdx.x * blockDim.x + threadIdx.x;
    if (idx >= total) return;
    int i   = idx & 63;
    int h   = (idx >> 6) % nh;
    int row = idx / (nh * 64);
    int tpos = row & (TSEQ - 1);
    float inv = powf(10000.0f, -(float)i * (1.0f / 64.0f));
    float ang = (float)tpos * inv;
    float s, c;
    sincosf(ang, &s, &c);
    size_t base = (size_t)row * (nh * 128) + h * 128 + i;
    float x1 = X[base];
    float x2 = X[base + 64];
    X[base]      = x1 * c - x2 * s;
    X[base + 64] = x2 * c + x1 * s;
}

// ---------------------------------------------------------------------------
// Flash attention, fp32, causal, GQA (q head h -> kv head h/2).
// Block: one (b,h) and 64 query rows. 256 threads = 16x16.
// Thread (ty,tx): S microtile 4x4 (rows ty*4.., keys tx*4..),
//                 O microtile 4x8 (rows ty*4.., dims tx*8..).
// Smem: Qt[128][65] (transposed, +pad), Kt[128][65] (Pst[64][64] overlays Kt),
//       Vs[64][128].
// ---------------------------------------------------------------------------
#define ATTN_SMEM_FLOATS (2 * 128 * 65 + 64 * 128)
#define ATTN_SMEM_BYTES  (ATTN_SMEM_FLOATS * 4)

__global__ __launch_bounds__(256) void attn_kernel(const float* __restrict__ Q,
                                                   const float* __restrict__ K,
                                                   const float* __restrict__ V,
                                                   float* __restrict__ AO) {
    extern __shared__ float sm[];
    float* Qt  = sm;                  // [128][65]
    float* Kt  = sm + 128 * 65;       // [128][65]
    float* Vs  = sm + 2 * 128 * 65;   // [64][128]
    float* Pst = Kt;                  // [64][64] overlay (P^T: [key][row])

    const int t  = threadIdx.x;
    const int tx = t & 15;
    const int ty = t >> 4;
    const int qb = blockIdx.x;        // query block 0..7
    const int bh = blockIdx.y;        // 0..127
    const int b   = bh >> 3;
    const int h   = bh & 7;
    const int kvh = h >> 1;
    const float scale = 0.08838834764831845f;   // 1/sqrt(128)

    const int qrow0 = b * TSEQ + qb * 64;

    // Load Q tile (64 rows x 128 d), transposed into Qt[d][row]
#pragma unroll
    for (int j = 0; j < 8; j++) {
        int fid = j * 256 + t;               // 2048 float4's
        int r   = fid >> 5;                  // 0..63
        int d0  = (fid & 31) * 4;            // 0..124
        float4 v = *reinterpret_cast<const float4*>(
            &Q[(size_t)(qrow0 + r) * 1024 + h * 128 + d0]);
        Qt[(d0 + 0) * 65 + r] = v.x;
        Qt[(d0 + 1) * 65 + r] = v.y;
        Qt[(d0 + 2) * 65 + r] = v.z;
        Qt[(d0 + 3) * 65 + r] = v.w;
    }

    float o[4][8];
    float m_i[4], l_i[4];
#pragma unroll
    for (int i = 0; i < 4; i++) {
        m_i[i] = -1e30f;
        l_i[i] = 0.f;
#pragma unroll
        for (int j = 0; j < 8; j++) o[i][j] = 0.f;
    }

    for (int kt = 0; kt <= qb; kt++) {
        __syncthreads();   // Kt/Pst/Vs free for reuse
        const int krow0 = b * TSEQ + kt * 64;
#pragma unroll
        for (int j = 0; j < 8; j++) {
            int fid = j * 256 + t;
            int r   = fid >> 5;
            int d0  = (fid & 31) * 4;
            float4 kv = *reinterpret_cast<const float4*>(
                &K[(size_t)(krow0 + r) * 512 + kvh * 128 + d0]);
            Kt[(d0 + 0) * 65 + r] = kv.x;
            Kt[(d0 + 1) * 65 + r] = kv.y;
            Kt[(d0 + 2) * 65 + r] = kv.z;
            Kt[(d0 + 3) * 65 + r] = kv.w;
            float4 vv = *reinterpret_cast<const float4*>(
                &V[(size_t)(krow0 + r) * 512 + kvh * 128 + d0]);
            *reinterpret_cast<float4*>(&Vs[r * 128 + d0]) = vv;
        }
        __syncthreads();

        // S = Q K^T  (4x4 per thread)
        float s_acc[4][4];
#pragma unroll
        for (int i = 0; i < 4; i++)
#pragma unroll
            for (int j = 0; j < 4; j++) s_acc[i][j] = 0.f;

#pragma unroll 2
        for (int d = 0; d < 128; d++) {
            float qv[4], kv[4];
#pragma unroll
            for (int i = 0; i < 4; i++) qv[i] = Qt[d * 65 + ty * 4 + i];
#pragma unroll
            for (int j = 0; j < 4; j++) kv[j] = Kt[d * 65 + tx * 4 + j];
#pragma unroll
            for (int i = 0; i < 4; i++)
#pragma unroll
                for (int j = 0; j < 4; j++)
                    s_acc[i][j] += qv[i] * kv[j];
        }

        // scale + causal mask + online softmax (row stats over 16-lane group)
#pragma unroll
        for (int i = 0; i < 4; i++) {
            int qr = qb * 64 + ty * 4 + i;
            float rmax = -1e30f;
#pragma unroll
            for (int j = 0; j < 4; j++) {
                float sv = s_acc[i][j] * scale;
                int kc = kt * 64 + tx * 4 + j;
                if (kc > qr) sv = -1e30f;
                s_acc[i][j] = sv;
                rmax = fmaxf(rmax, sv);
            }
#pragma unroll
            for (int off = 1; off < 16; off <<= 1)
                rmax = fmaxf(rmax, __shfl_xor_sync(0xffffffffu, rmax, off));
            float m_new = fmaxf(m_i[i], rmax);
            float corr  = __expf(m_i[i] - m_new);
            float rsum  = 0.f;
#pragma unroll
            for (int j = 0; j < 4; j++) {
                float p = __expf(s_acc[i][j] - m_new);
                s_acc[i][j] = p;
                rsum += p;
            }
#pragma unroll
            for (int off = 1; off < 16; off <<= 1)
                rsum += __shfl_xor_sync(0xffffffffu, rsum, off);
            l_i[i] = l_i[i] * corr + rsum;
            m_i[i] = m_new;
#pragma unroll
            for (int j = 0; j < 8; j++) o[i][j] *= corr;
        }

        __syncthreads();   // all threads done reading Kt before Pst overlay
#pragma unroll
        for (int i = 0; i < 4; i++)
#pragma unroll
            for (int j = 0; j < 4; j++)
                Pst[(tx * 4 + j) * 64 + ty * 4 + i] = s_acc[i][j];
        __syncthreads();

        // O += P V   (4x8 per thread)
#pragma unroll 2
        for (int k = 0; k < 64; k++) {
            float4 p4 = *reinterpret_cast<float4*>(&Pst[k * 64 + ty * 4]);
            float4 v0 = *reinterpret_cast<float4*>(&Vs[k * 128 + tx * 8]);
            float4 v1 = *reinterpret_cast<float4*>(&Vs[k * 128 + tx * 8 + 4]);
            float pa[4] = {p4.x, p4.y, p4.z, p4.w};
            float vb[8] = {v0.x, v0.y, v0.z, v0.w, v1.x, v1.y, v1.z, v1.w};
#pragma unroll
            for (int i = 0; i < 4; i++)
#pragma unroll
                for (int j = 0; j < 8; j++)
                    o[i][j] += pa[i] * vb[j];
        }
    }

    // epilogue: normalize, write AO[(b,t), h*128 + d]
#pragma unroll
    for (int i = 0; i < 4; i++) {
        float inv = 1.0f / l_i[i];
        size_t off = (size_t)(qrow0 + ty * 4 + i) * 1024 + h * 128 + tx * 8;
        float4 c0 = make_float4(o[i][0] * inv, o[i][1] * inv, o[i][2] * inv, o[i][3] * inv);
        float4 c1 = make_float4(o[i][4] * inv, o[i][5] * inv, o[i][6] * inv, o[i][7] * inv);
        *reinterpret_cast<float4*>(&AO[off])     = c0;
        *reinterpret_cast<float4*>(&AO[off + 4]) = c1;
    }
}

// ---------------------------------------------------------------------------
extern "C" void kernel_launch(void* const* d_in, const int* in_sizes, int n_in,
                              void* d_out, int out_size) {
    const float* hs = (const float*)d_in[0];
    const float* Wq = (const float*)d_in[1];
    const float* Wk = (const float*)d_in[2];
    const float* Wv = (const float*)d_in[3];
    const float* Wo = (const float*)d_in[4];
    float* out = (float*)d_out;

    float *Qp, *Kp, *Vp, *AOp;
    cudaGetSymbolAddress((void**)&Qp,  g_Q);
    cudaGetSymbolAddress((void**)&Kp,  g_K);
    cudaGetSymbolAddress((void**)&Vp,  g_V);
    cudaGetSymbolAddress((void**)&AOp, g_AO);

    cudaFuncSetAttribute(attn_kernel, cudaFuncAttributeMaxDynamicSharedMemorySize,
                         ATTN_SMEM_BYTES);

    // Projections
    sgemm128<<<dim3(1024 / 128, BT / 128), 256>>>(hs, Wq, Qp, BT, 1024, 1024);
    sgemm128<<<dim3(512 / 128,  BT / 128), 256>>>(hs, Wk, Kp, BT, 512, 1024);
    sgemm128<<<dim3(512 / 128,  BT / 128), 256>>>(hs, Wv, Vp, BT, 512, 1024);

    // RoPE on Q and K
    {
        int totq = BT * NHQ * 64;
        int totk = BT * NKVH * 64;
        rope_kernel<<<(totq + 255) / 256, 256>>>(Qp, NHQ,  totq);
        rope_kernel<<<(totk + 255) / 256, 256>>>(Kp, NKVH, totk);
    }

    // Attention
    attn_kernel<<<dim3(TSEQ / 64, 16 * NHQ), 256, ATTN_SMEM_BYTES>>>(Qp, Kp, Vp, AOp);

    // Output projection
    sgemm128<<<dim3(1024 / 128, BT / 128), 256>>>(AOp, Wo, out, BT, 1024, 1024);
}

// round 4
// speedup vs baseline: 2.0594x; 2.0594x over previous
#include <cuda_runtime.h>
#include <math.h>
#include <stdint.h>

// Problem constants
#define BT    8192     // B*T
#define TSEQ  512
#define NHQ   8
#define NKVH  4
#define DH    128

// Scratch (device globals: allocation-free contract)
__device__ float    g_Q  [BT * 1024];
__device__ float    g_K  [BT * 512];
__device__ float    g_V  [BT * 512];
__device__ float    g_AO [BT * 1024];
__device__ uint32_t g_WtQ[1024 * 1024];   // Wq^T  [N=1024][K=1024] tf32 bits
__device__ uint32_t g_WtK[512  * 1024];   // Wk^T  [512][1024]
__device__ uint32_t g_WtV[512  * 1024];   // Wv^T  [512][1024]
__device__ uint32_t g_WtO[1024 * 1024];   // Wo^T  [1024][1024]

__device__ __forceinline__ uint32_t f2tf32(float f) {
    uint32_t r;
    asm("cvt.rna.tf32.f32 %0, %1;" : "=r"(r) : "f"(f));
    return r;
}

__device__ __forceinline__ void mma_tf32(float* c, const uint32_t* a,
                                         uint32_t b0, uint32_t b1) {
    asm volatile(
        "mma.sync.aligned.m16n8k8.row.col.f32.tf32.tf32.f32 "
        "{%0,%1,%2,%3}, {%4,%5,%6,%7}, {%8,%9}, {%0,%1,%2,%3};"
        : "+f"(c[0]), "+f"(c[1]), "+f"(c[2]), "+f"(c[3])
        : "r"(a[0]), "r"(a[1]), "r"(a[2]), "r"(a[3]), "r"(b0), "r"(b1));
}

// ---------------------------------------------------------------------------
// Weight transpose + tf32 convert: W[K,N] fp32 -> Wt[N,K] tf32 bits
// ---------------------------------------------------------------------------
__global__ void transpose_tf32(const float* __restrict__ W, uint32_t* __restrict__ Wt,
                               int K, int N) {
    __shared__ float tile[32][33];
    int bx = blockIdx.x * 32;   // n base
    int by = blockIdx.y * 32;   // k base
    int tx = threadIdx.x, ty = threadIdx.y;
#pragma unroll
    for (int i = 0; i < 32; i += 8)
        tile[ty + i][tx] = W[(size_t)(by + ty + i) * N + bx + tx];
    __syncthreads();
#pragma unroll
    for (int i = 0; i < 32; i += 8)
        Wt[(size_t)(bx + ty + i) * K + by + tx] = f2tf32(tile[tx][ty + i]);
}

// ---------------------------------------------------------------------------
// tf32 mma.sync GEMM: C[M,N] = A[M,K] (fp32, K-major) @ Bt[N,K] (tf32 bits)
// 128x128 CTA tile, BK=32, 256 threads, warp grid 4(M) x 2(N), warp tile 32x64.
// Smem stride 36 words => conflict-free fragment loads.
// ---------------------------------------------------------------------------
#define LDSS 36

__global__ __launch_bounds__(256) void tf32_gemm(const float* __restrict__ A,
                                                 const uint32_t* __restrict__ Bt,
                                                 float* __restrict__ C,
                                                 int N, int K) {
    __shared__ uint32_t As[128 * LDSS];
    __shared__ uint32_t Bs[128 * LDSS];

    const int t    = threadIdx.x;
    const int lane = t & 31;
    const int wid  = t >> 5;
    const int warp_m = wid & 3;    // 0..3  -> rows warp_m*32
    const int warp_n = wid >> 2;   // 0..1  -> cols warp_n*64
    const int row0 = blockIdx.y * 128;
    const int col0 = blockIdx.x * 128;

    float acc[2][8][4];
#pragma unroll
    for (int mi = 0; mi < 2; mi++)
#pragma unroll
        for (int ni = 0; ni < 8; ni++)
#pragma unroll
            for (int x = 0; x < 4; x++) acc[mi][ni][x] = 0.f;

    const int r_ = t >> 3;   // 0..31
    const int c4 = t & 7;    // float4 column in 32-wide K tile
    const int ar = lane >> 2, ak = lane & 3;

    const int nkt = K >> 5;
    for (int kt = 0; kt < nkt; kt++) {
        // global -> smem (A converted to tf32 on the fly)
#pragma unroll
        for (int j = 0; j < 4; j++) {
            int r = r_ + j * 32;
            float4 av = *reinterpret_cast<const float4*>(
                &A[(size_t)(row0 + r) * K + kt * 32 + c4 * 4]);
            uint4 bv = *reinterpret_cast<const uint4*>(
                &Bt[(size_t)(col0 + r) * K + kt * 32 + c4 * 4]);
            int base = r * LDSS + c4 * 4;
            As[base + 0] = f2tf32(av.x);
            As[base + 1] = f2tf32(av.y);
            As[base + 2] = f2tf32(av.z);
            As[base + 3] = f2tf32(av.w);
            Bs[base + 0] = bv.x;
            Bs[base + 1] = bv.y;
            Bs[base + 2] = bv.z;
            Bs[base + 3] = bv.w;
        }
        __syncthreads();

#pragma unroll
        for (int ks = 0; ks < 4; ks++) {
            const int kc = ks * 8;
            uint32_t a[2][4];
#pragma unroll
            for (int mi = 0; mi < 2; mi++) {
                int rb = warp_m * 32 + mi * 16 + ar;
                a[mi][0] = As[rb * LDSS + kc + ak];
                a[mi][1] = As[(rb + 8) * LDSS + kc + ak];
                a[mi][2] = As[rb * LDSS + kc + 4 + ak];
                a[mi][3] = As[(rb + 8) * LDSS + kc + 4 + ak];
            }
#pragma unroll
            for (int ni = 0; ni < 8; ni++) {
                int cb = (warp_n * 64 + ni * 8 + ar) * LDSS + kc + ak;
                uint32_t b0 = Bs[cb];
                uint32_t b1 = Bs[cb + 4];
                mma_tf32(acc[0][ni], a[0], b0, b1);
                mma_tf32(acc[1][ni], a[1], b0, b1);
            }
        }
        __syncthreads();
    }

    // Epilogue: c0,c1 at (row, 2c), c2,c3 at (row+8, 2c)
#pragma unroll
    for (int mi = 0; mi < 2; mi++) {
        int rb = row0 + warp_m * 32 + mi * 16 + (lane >> 2);
#pragma unroll
        for (int ni = 0; ni < 8; ni++) {
            int cb = col0 + warp_n * 64 + ni * 8 + 2 * (lane & 3);
            *reinterpret_cast<float2*>(&C[(size_t)rb * N + cb]) =
                make_float2(acc[mi][ni][0], acc[mi][ni][1]);
            *reinterpret_cast<float2*>(&C[(size_t)(rb + 8) * N + cb]) =
                make_float2(acc[mi][ni][2], acc[mi][ni][3]);
        }
    }
}

// ---------------------------------------------------------------------------
// RoPE, in place on X[BT, nh*128].
// ---------------------------------------------------------------------------
__global__ void rope_kernel(float* __restrict__ X, int nh, int total) {
    int idx = blockIdx.x * blockDim.x + threadIdx.x;
    if (idx >= total) return;
    int i   = idx & 63;
    int h   = (idx >> 6) % nh;
    int row = idx / (nh * 64);
    int tpos = row & (TSEQ - 1);
    float inv = powf(10000.0f, -(float)i * (1.0f / 64.0f));
    float ang = (float)tpos * inv;
    float s, c;
    sincosf(ang, &s, &c);
    size_t base = (size_t)row * (nh * 128) + h * 128 + i;
    float x1 = X[base];
    float x2 = X[base + 64];
    X[base]      = x1 * c - x2 * s;
    X[base + 64] = x2 * c + x1 * s;
}

// ---------------------------------------------------------------------------
// Flash attention, fp32, causal, GQA (q head h -> kv head h/2).
// ---------------------------------------------------------------------------
#define ATTN_SMEM_FLOATS (2 * 128 * 65 + 64 * 128)
#define ATTN_SMEM_BYTES  (ATTN_SMEM_FLOATS * 4)

__global__ __launch_bounds__(256) void attn_kernel(const float* __restrict__ Q,
                                                   const float* __restrict__ K,
                                                   const float* __restrict__ V,
                                                   float* __restrict__ AO) {
    extern __shared__ float sm[];
    float* Qt  = sm;
    float* Kt  = sm + 128 * 65;
    float* Vs  = sm + 2 * 128 * 65;
    float* Pst = Kt;

    const int t  = threadIdx.x;
    const int tx = t & 15;
    const int ty = t >> 4;
    const int qb = blockIdx.x;
    const int bh = blockIdx.y;
    const int b   = bh >> 3;
    const int h   = bh & 7;
    const int kvh = h >> 1;
    const float scale = 0.08838834764831845f;

    const int qrow0 = b * TSEQ + qb * 64;

#pragma unroll
    for (int j = 0; j < 8; j++) {
        int fid = j * 256 + t;
        int r   = fid >> 5;
        int d0  = (fid & 31) * 4;
        float4 v = *reinterpret_cast<const float4*>(
            &Q[(size_t)(qrow0 + r) * 1024 + h * 128 + d0]);
        Qt[(d0 + 0) * 65 + r] = v.x;
        Qt[(d0 + 1) * 65 + r] = v.y;
        Qt[(d0 + 2) * 65 + r] = v.z;
        Qt[(d0 + 3) * 65 + r] = v.w;
    }

    float o[4][8];
    float m_i[4], l_i[4];
#pragma unroll
    for (int i = 0; i < 4; i++) {
        m_i[i] = -1e30f;
        l_i[i] = 0.f;
#pragma unroll
        for (int j = 0; j < 8; j++) o[i][j] = 0.f;
    }

    for (int kt = 0; kt <= qb; kt++) {
        __syncthreads();
        const int krow0 = b * TSEQ + kt * 64;
#pragma unroll
        for (int j = 0; j < 8; j++) {
            int fid = j * 256 + t;
            int r   = fid >> 5;
            int d0  = (fid & 31) * 4;
            float4 kv = *reinterpret_cast<const float4*>(
                &K[(size_t)(krow0 + r) * 512 + kvh * 128 + d0]);
            Kt[(d0 + 0) * 65 + r] = kv.x;
            Kt[(d0 + 1) * 65 + r] = kv.y;
            Kt[(d0 + 2) * 65 + r] = kv.z;
            Kt[(d0 + 3) * 65 + r] = kv.w;
            float4 vv = *reinterpret_cast<const float4*>(
                &V[(size_t)(krow0 + r) * 512 + kvh * 128 + d0]);
            *reinterpret_cast<float4*>(&Vs[r * 128 + d0]) = vv;
        }
        __syncthreads();

        float s_acc[4][4];
#pragma unroll
        for (int i = 0; i < 4; i++)
#pragma unroll
            for (int j = 0; j < 4; j++) s_acc[i][j] = 0.f;

#pragma unroll 2
        for (int d = 0; d < 128; d++) {
            float qv[4], kv[4];
#pragma unroll
            for (int i = 0; i < 4; i++) qv[i] = Qt[d * 65 + ty * 4 + i];
#pragma unroll
            for (int j = 0; j < 4; j++) kv[j] = Kt[d * 65 + tx * 4 + j];
#pragma unroll
            for (int i = 0; i < 4; i++)
#pragma unroll
                for (int j = 0; j < 4; j++)
                    s_acc[i][j] += qv[i] * kv[j];
        }

#pragma unroll
        for (int i = 0; i < 4; i++) {
            int qr = qb * 64 + ty * 4 + i;
            float rmax = -1e30f;
#pragma unroll
            for (int j = 0; j < 4; j++) {
                float sv = s_acc[i][j] * scale;
                int kc = kt * 64 + tx * 4 + j;
                if (kc > qr) sv = -1e30f;
                s_acc[i][j] = sv;
                rmax = fmaxf(rmax, sv);
            }
#pragma unroll
            for (int off = 1; off < 16; off <<= 1)
                rmax = fmaxf(rmax, __shfl_xor_sync(0xffffffffu, rmax, off));
            float m_new = fmaxf(m_i[i], rmax);
            float corr  = __expf(m_i[i] - m_new);
            float rsum  = 0.f;
#pragma unroll
            for (int j = 0; j < 4; j++) {
                float p = __expf(s_acc[i][j] - m_new);
                s_acc[i][j] = p;
                rsum += p;
            }
#pragma unroll
            for (int off = 1; off < 16; off <<= 1)
                rsum += __shfl_xor_sync(0xffffffffu, rsum, off);
            l_i[i] = l_i[i] * corr + rsum;
            m_i[i] = m_new;
#pragma unroll
            for (int j = 0; j < 8; j++) o[i][j] *= corr;
        }

        __syncthreads();
#pragma unroll
        for (int i = 0; i < 4; i++)
#pragma unroll
            for (int j = 0; j < 4; j++)
                Pst[(tx * 4 + j) * 64 + ty * 4 + i] = s_acc[i][j];
        __syncthreads();

#pragma unroll 2
        for (int k = 0; k < 64; k++) {
            float4 p4 = *reinterpret_cast<float4*>(&Pst[k * 64 + ty * 4]);
            float4 v0 = *reinterpret_cast<float4*>(&Vs[k * 128 + tx * 8]);
            float4 v1 = *reinterpret_cast<float4*>(&Vs[k * 128 + tx * 8 + 4]);
            float pa[4] = {p4.x, p4.y, p4.z, p4.w};
            float vb[8] = {v0.x, v0.y, v0.z, v0.w, v1.x, v1.y, v1.z, v1.w};
#pragma unroll
            for (int i = 0; i < 4; i++)
#pragma unroll
                for (int j = 0; j < 8; j++)
                    o[i][j] += pa[i] * vb[j];
        }
    }

#pragma unroll
    for (int i = 0; i < 4; i++) {
        float inv = 1.0f / l_i[i];
        size_t off = (size_t)(qrow0 + ty * 4 + i) * 1024 + h * 128 + tx * 8;
        float4 c0 = make_float4(o[i][0] * inv, o[i][1] * inv, o[i][2] * inv, o[i][3] * inv);
        float4 c1 = make_float4(o[i][4] * inv, o[i][5] * inv, o[i][6] * inv, o[i][7] * inv);
        *reinterpret_cast<float4*>(&AO[off])     = c0;
        *reinterpret_cast<float4*>(&AO[off + 4]) = c1;
    }
}

// ---------------------------------------------------------------------------
extern "C" void kernel_launch(void* const* d_in, const int* in_sizes, int n_in,
                              void* d_out, int out_size) {
    const float* hs = (const float*)d_in[0];
    const float* Wq = (const float*)d_in[1];
    const float* Wk = (const float*)d_in[2];
    const float* Wv = (const float*)d_in[3];
    const float* Wo = (const float*)d_in[4];
    float* out = (float*)d_out;

    float *Qp, *Kp, *Vp, *AOp;
    uint32_t *WtQ, *WtK, *WtV, *WtO;
    cudaGetSymbolAddress((void**)&Qp,  g_Q);
    cudaGetSymbolAddress((void**)&Kp,  g_K);
    cudaGetSymbolAddress((void**)&Vp,  g_V);
    cudaGetSymbolAddress((void**)&AOp, g_AO);
    cudaGetSymbolAddress((void**)&WtQ, g_WtQ);
    cudaGetSymbolAddress((void**)&WtK, g_WtK);
    cudaGetSymbolAddress((void**)&WtV, g_WtV);
    cudaGetSymbolAddress((void**)&WtO, g_WtO);

    cudaFuncSetAttribute(attn_kernel, cudaFuncAttributeMaxDynamicSharedMemorySize,
                         ATTN_SMEM_BYTES);

    dim3 t32(32, 8);
    transpose_tf32<<<dim3(1024 / 32, 1024 / 32), t32>>>(Wq, WtQ, 1024, 1024);
    transpose_tf32<<<dim3(512  / 32, 1024 / 32), t32>>>(Wk, WtK, 1024, 512);
    transpose_tf32<<<dim3(512  / 32, 1024 / 32), t32>>>(Wv, WtV, 1024, 512);
    transpose_tf32<<<dim3(1024 / 32, 1024 / 32), t32>>>(Wo, WtO, 1024, 1024);

    // Projections (tf32 mma.sync)
    tf32_gemm<<<dim3(1024 / 128, BT / 128), 256>>>(hs, WtQ, Qp, 1024, 1024);
    tf32_gemm<<<dim3(512  / 128, BT / 128), 256>>>(hs, WtK, Kp, 512, 1024);
    tf32_gemm<<<dim3(512  / 128, BT / 128), 256>>>(hs, WtV, Vp, 512, 1024);

    // RoPE on Q and K
    {
        int totq = BT * NHQ * 64;
        int totk = BT * NKVH * 64;
        rope_kernel<<<(totq + 255) / 256, 256>>>(Qp, NHQ,  totq);
        rope_kernel<<<(totk + 255) / 256, 256>>>(Kp, NKVH, totk);
    }

    // Attention
    attn_kernel<<<dim3(TSEQ / 64, 16 * NHQ), 256, ATTN_SMEM_BYTES>>>(Qp, Kp, Vp, AOp);

    // Output projection
    tf32_gemm<<<dim3(1024 / 128, BT / 128), 256>>>(AOp, WtO, out, 1024, 1024);
}

// round 8
// speedup vs baseline: 3.1094x; 1.5099x over previous
#include <cuda_runtime.h>
#include <math.h>
#include <stdint.h>

// Problem constants
#define BT    8192     // B*T
#define TSEQ  512
#define NHQ   8
#define NKVH  4
#define DH    128

// Scratch (device globals: allocation-free contract)
__device__ float    g_Q  [BT * 1024];
__device__ float    g_K  [BT * 512];
__device__ float    g_V  [BT * 512];
__device__ float    g_AO [BT * 1024];
__device__ uint32_t g_WtQ[1024 * 1024];   // Wq^T  [N=1024][K=1024] tf32 bits
__device__ uint32_t g_WtK[512  * 1024];
__device__ uint32_t g_WtV[512  * 1024];
__device__ uint32_t g_WtO[1024 * 1024];

__device__ __forceinline__ uint32_t f2tf32(float f) {
    uint32_t r;
    asm("cvt.rna.tf32.f32 %0, %1;" : "=r"(r) : "f"(f));
    return r;
}

__device__ __forceinline__ void mma_tf32(float* c, const uint32_t* a,
                                         uint32_t b0, uint32_t b1) {
    asm volatile(
        "mma.sync.aligned.m16n8k8.row.col.f32.tf32.tf32.f32 "
        "{%0,%1,%2,%3}, {%4,%5,%6,%7}, {%8,%9}, {%0,%1,%2,%3};"
        : "+f"(c[0]), "+f"(c[1]), "+f"(c[2]), "+f"(c[3])
        : "r"(a[0]), "r"(a[1]), "r"(a[2]), "r"(a[3]), "r"(b0), "r"(b1));
}

// ---------------------------------------------------------------------------
// Weight transpose + tf32 convert: W[K,N] fp32 -> Wt[N,K] tf32 bits
// ---------------------------------------------------------------------------
__global__ void transpose_tf32(const float* __restrict__ W, uint32_t* __restrict__ Wt,
                               int K, int N) {
    __shared__ float tile[32][33];
    int bx = blockIdx.x * 32;
    int by = blockIdx.y * 32;
    int tx = threadIdx.x, ty = threadIdx.y;
#pragma unroll
    for (int i = 0; i < 32; i += 8)
        tile[ty + i][tx] = W[(size_t)(by + ty + i) * N + bx + tx];
    __syncthreads();
#pragma unroll
    for (int i = 0; i < 32; i += 8)
        Wt[(size_t)(bx + ty + i) * K + by + tx] = f2tf32(tile[tx][ty + i]);
}

// ---------------------------------------------------------------------------
// tf32 mma.sync GEMM with register prefetch double-buffering.
// C[M,N] = A[M,K] (fp32, K-major) @ Bt[N,K] (tf32). 128x128 tile, BK=32.
// ---------------------------------------------------------------------------
#define LDSS 36

__global__ __launch_bounds__(256) void tf32_gemm(const float* __restrict__ A,
                                                 const uint32_t* __restrict__ Bt,
                                                 float* __restrict__ C,
                                                 int N, int K) {
    __shared__ uint32_t As[128 * LDSS];
    __shared__ uint32_t Bs[128 * LDSS];

    const int t    = threadIdx.x;
    const int lane = t & 31;
    const int wid  = t >> 5;
    const int warp_m = wid & 3;
    const int warp_n = wid >> 2;
    const int row0 = blockIdx.y * 128;
    const int col0 = blockIdx.x * 128;

    float acc[2][8][4];
#pragma unroll
    for (int mi = 0; mi < 2; mi++)
#pragma unroll
        for (int ni = 0; ni < 8; ni++)
#pragma unroll
            for (int x = 0; x < 4; x++) acc[mi][ni][x] = 0.f;

    const int r_ = t >> 3;
    const int c4 = t & 7;
    const int ar_ = lane >> 2, ak = lane & 3;

    float4 areg[4];
    uint4  breg[4];
    auto LOADR = [&](int kt) {
#pragma unroll
        for (int j = 0; j < 4; j++) {
            int r = r_ + j * 32;
            areg[j] = *reinterpret_cast<const float4*>(
                &A[(size_t)(row0 + r) * K + kt * 32 + c4 * 4]);
            breg[j] = *reinterpret_cast<const uint4*>(
                &Bt[(size_t)(col0 + r) * K + kt * 32 + c4 * 4]);
        }
    };

    const int nkt = K >> 5;
    LOADR(0);
    for (int kt = 0; kt < nkt; kt++) {
#pragma unroll
        for (int j = 0; j < 4; j++) {
            int base = (r_ + j * 32) * LDSS + c4 * 4;
            As[base + 0] = f2tf32(areg[j].x);
            As[base + 1] = f2tf32(areg[j].y);
            As[base + 2] = f2tf32(areg[j].z);
            As[base + 3] = f2tf32(areg[j].w);
            Bs[base + 0] = breg[j].x;
            Bs[base + 1] = breg[j].y;
            Bs[base + 2] = breg[j].z;
            Bs[base + 3] = breg[j].w;
        }
        __syncthreads();
        if (kt + 1 < nkt) LOADR(kt + 1);   // prefetch overlaps mma below

#pragma unroll
        for (int ks = 0; ks < 4; ks++) {
            const int kc = ks * 8;
            uint32_t a[2][4];
#pragma unroll
            for (int mi = 0; mi < 2; mi++) {
                int rb = warp_m * 32 + mi * 16 + ar_;
                a[mi][0] = As[rb * LDSS + kc + ak];
                a[mi][1] = As[(rb + 8) * LDSS + kc + ak];
                a[mi][2] = As[rb * LDSS + kc + 4 + ak];
                a[mi][3] = As[(rb + 8) * LDSS + kc + 4 + ak];
            }
#pragma unroll
            for (int ni = 0; ni < 8; ni++) {
                int cb = (warp_n * 64 + ni * 8 + ar_) * LDSS + kc + ak;
                uint32_t b0 = Bs[cb];
                uint32_t b1 = Bs[cb + 4];
                mma_tf32(acc[0][ni], a[0], b0, b1);
                mma_tf32(acc[1][ni], a[1], b0, b1);
            }
        }
        __syncthreads();
    }

#pragma unroll
    for (int mi = 0; mi < 2; mi++) {
        int rb = row0 + warp_m * 32 + mi * 16 + (lane >> 2);
#pragma unroll
        for (int ni = 0; ni < 8; ni++) {
            int cb = col0 + warp_n * 64 + ni * 8 + 2 * (lane & 3);
            *reinterpret_cast<float2*>(&C[(size_t)rb * N + cb]) =
                make_float2(acc[mi][ni][0], acc[mi][ni][1]);
            *reinterpret_cast<float2*>(&C[(size_t)(rb + 8) * N + cb]) =
                make_float2(acc[mi][ni][2], acc[mi][ni][3]);
        }
    }
}

// ---------------------------------------------------------------------------
// RoPE, in place on X[BT, nh*128].
// ---------------------------------------------------------------------------
__global__ void rope_kernel(float* __restrict__ X, int nh, int total) {
    int idx = blockIdx.x * blockDim.x + threadIdx.x;
    if (idx >= total) return;
    int i   = idx & 63;
    int h   = (idx >> 6) % nh;
    int row = idx / (nh * 64);
    int tpos = row & (TSEQ - 1);
    float inv = powf(10000.0f, -(float)i * (1.0f / 64.0f));
    float ang = (float)tpos * inv;
    float s, c;
    sincosf(ang, &s, &c);
    size_t base = (size_t)row * (nh * 128) + h * 128 + i;
    float x1 = X[base];
    float x2 = X[base + 64];
    X[base]      = x1 * c - x2 * s;
    X[base + 64] = x2 * c + x1 * s;
}

// ---------------------------------------------------------------------------
// Tensorized flash attention (tf32 mma.sync), causal, GQA.
// CTA: one (b,h), 128 query rows. 8 warps; warp w owns q-rows w*16..+15.
// Qs/Ks stride 132 (full d=128 resident). Vs as [dchunk(16)][key(64)][8].
// ---------------------------------------------------------------------------
#define QK_LDS 132
#define AP_LDS 68
#define ATTN2_SMEM_WORDS (128 * QK_LDS + 64 * QK_LDS + 16 * 64 * 8 + 128 * AP_LDS)
#define ATTN2_SMEM_BYTES (ATTN2_SMEM_WORDS * 4)

__global__ __launch_bounds__(256) void attn_mma(const float* __restrict__ Q,
                                                const float* __restrict__ K,
                                                const float* __restrict__ V,
                                                float* __restrict__ AO) {
    extern __shared__ uint32_t sm[];
    uint32_t* Qs = sm;                              // [128][132]
    uint32_t* Ks = Qs + 128 * QK_LDS;               // [64][132]
    uint32_t* Vs = Ks + 64 * QK_LDS;                // [16][64][8]
    uint32_t* Ps = Vs + 16 * 64 * 8;                // [128][68]

    const int t    = threadIdx.x;
    const int lane = t & 31;
    const int w    = t >> 5;
    const int qb   = 3 - blockIdx.x;                // heavy blocks first
    const int bh   = blockIdx.y;
    const int b    = bh >> 3;
    const int h    = bh & 7;
    const int kvh  = h >> 1;
    const int qrow0 = b * TSEQ + qb * 128;
    const int g = lane >> 2, c = lane & 3;
    const float scale = 0.08838834764831845f;

    // Load Q tile (128 rows x 128 d) -> Qs (tf32)
#pragma unroll
    for (int j = 0; j < 16; j++) {
        int fid = j * 256 + t;
        int r   = fid >> 5;            // 0..127
        int d0  = (fid & 31) * 4;      // 0..124
        float4 v = *reinterpret_cast<const float4*>(
            &Q[(size_t)(qrow0 + r) * 1024 + h * 128 + d0]);
        int base = r * QK_LDS + d0;
        Qs[base + 0] = f2tf32(v.x);
        Qs[base + 1] = f2tf32(v.y);
        Qs[base + 2] = f2tf32(v.z);
        Qs[base + 3] = f2tf32(v.w);
    }

    float o[16][4];
#pragma unroll
    for (int ni = 0; ni < 16; ni++)
#pragma unroll
        for (int x = 0; x < 4; x++) o[ni][x] = 0.f;
    float m_i[2] = {-1e30f, -1e30f};
    float l_i[2] = {0.f, 0.f};

    const int nkt = 2 * qb + 2;
    for (int kt = 0; kt < nkt; kt++) {
        __syncthreads();   // Q visible (1st iter); prev-iter consumers done
        const int krow0 = b * TSEQ + kt * 64;
#pragma unroll
        for (int j = 0; j < 8; j++) {
            int fid = j * 256 + t;
            int r   = fid >> 5;            // 0..63
            int d0  = (fid & 31) * 4;      // 0..124
            float4 kv = *reinterpret_cast<const float4*>(
                &K[(size_t)(krow0 + r) * 512 + kvh * 128 + d0]);
            int base = r * QK_LDS + d0;
            Ks[base + 0] = f2tf32(kv.x);
            Ks[base + 1] = f2tf32(kv.y);
            Ks[base + 2] = f2tf32(kv.z);
            Ks[base + 3] = f2tf32(kv.w);
            float4 vv = *reinterpret_cast<const float4*>(
                &V[(size_t)(krow0 + r) * 512 + kvh * 128 + d0]);
            uint32_t* vp = &Vs[(d0 >> 3) * 512 + r * 8 + (d0 & 7)];
            vp[0] = f2tf32(vv.x);
            vp[1] = f2tf32(vv.y);
            vp[2] = f2tf32(vv.z);
            vp[3] = f2tf32(vv.w);
        }
        __syncthreads();

        // S = Q K^T  (warp rows w*16..+15 x 64 keys)
        float sacc[8][4];
#pragma unroll
        for (int ni = 0; ni < 8; ni++)
#pragma unroll
            for (int x = 0; x < 4; x++) sacc[ni][x] = 0.f;

#pragma unroll
        for (int ks = 0; ks < 16; ks++) {
            const int kc = ks * 8;
            uint32_t a[4];
            int abase = (w * 16 + g) * QK_LDS + kc + c;
            a[0] = Qs[abase];
            a[1] = Qs[abase + 8 * QK_LDS];
            a[2] = Qs[abase + 4];
            a[3] = Qs[abase + 8 * QK_LDS + 4];
#pragma unroll
            for (int ni = 0; ni < 8; ni++) {
                int bb = (ni * 8 + g) * QK_LDS + kc + c;
                mma_tf32(sacc[ni], a, Ks[bb], Ks[bb + 4]);
            }
        }

        // online softmax: thread owns rows (row0) and (row0+8)
        const int row0 = qb * 128 + w * 16 + g;
        const bool diag = (kt >= 2 * qb);
        float rmax0 = -1e30f, rmax1 = -1e30f;
#pragma unroll
        for (int ni = 0; ni < 8; ni++) {
#pragma unroll
            for (int x = 0; x < 4; x++) {
                float sv = sacc[ni][x] * scale;
                if (diag) {
                    int col = kt * 64 + ni * 8 + 2 * c + (x & 1);
                    int row = row0 + ((x >= 2) ? 8 : 0);
                    if (col > row) sv = -1e30f;
                }
                sacc[ni][x] = sv;
                if (x < 2) rmax0 = fmaxf(rmax0, sv);
                else       rmax1 = fmaxf(rmax1, sv);
            }
        }
#pragma unroll
        for (int off = 1; off < 4; off <<= 1) {
            rmax0 = fmaxf(rmax0, __shfl_xor_sync(0xffffffffu, rmax0, off));
            rmax1 = fmaxf(rmax1, __shfl_xor_sync(0xffffffffu, rmax1, off));
        }
        float mn0 = fmaxf(m_i[0], rmax0);
        float mn1 = fmaxf(m_i[1], rmax1);
        float corr0 = __expf(m_i[0] - mn0);
        float corr1 = __expf(m_i[1] - mn1);
        float rsum0 = 0.f, rsum1 = 0.f;
#pragma unroll
        for (int ni = 0; ni < 8; ni++) {
            float p0 = __expf(sacc[ni][0] - mn0);
            float p1 = __expf(sacc[ni][1] - mn0);
            float p2 = __expf(sacc[ni][2] - mn1);
            float p3 = __expf(sacc[ni][3] - mn1);
            sacc[ni][0] = p0; sacc[ni][1] = p1;
            sacc[ni][2] = p2; sacc[ni][3] = p3;
            rsum0 += p0 + p1;
            rsum1 += p2 + p3;
        }
#pragma unroll
        for (int off = 1; off < 4; off <<= 1) {
            rsum0 += __shfl_xor_sync(0xffffffffu, rsum0, off);
            rsum1 += __shfl_xor_sync(0xffffffffu, rsum1, off);
        }
        l_i[0] = l_i[0] * corr0 + rsum0;
        l_i[1] = l_i[1] * corr1 + rsum1;
        m_i[0] = mn0;
        m_i[1] = mn1;
#pragma unroll
        for (int ni = 0; ni < 16; ni++) {
            o[ni][0] *= corr0; o[ni][1] *= corr0;
            o[ni][2] *= corr1; o[ni][3] *= corr1;
        }

        // P -> smem (tf32), warp-private rows
#pragma unroll
        for (int ni = 0; ni < 8; ni++) {
            int p0 = (w * 16 + g) * AP_LDS + ni * 8 + 2 * c;
            Ps[p0]     = f2tf32(sacc[ni][0]);
            Ps[p0 + 1] = f2tf32(sacc[ni][1]);
            int p1 = p0 + 8 * AP_LDS;
            Ps[p1]     = f2tf32(sacc[ni][2]);
            Ps[p1 + 1] = f2tf32(sacc[ni][3]);
        }
        __syncwarp();

        // O += P V
#pragma unroll
        for (int kc2 = 0; kc2 < 8; kc2++) {
            const int koff = kc2 * 8;
            uint32_t a[4];
            int abase = (w * 16 + g) * AP_LDS + koff + c;
            a[0] = Ps[abase];
            a[1] = Ps[abase + 8 * AP_LDS];
            a[2] = Ps[abase + 4];
            a[3] = Ps[abase + 8 * AP_LDS + 4];
#pragma unroll
            for (int ni = 0; ni < 16; ni++) {
                int vb = ni * 512 + (koff + c) * 8 + g;
                mma_tf32(o[ni], a, Vs[vb], Vs[vb + 32]);
            }
        }
    }

    // epilogue
    float inv0 = 1.0f / l_i[0];
    float inv1 = 1.0f / l_i[1];
    const int orow = qrow0 + w * 16 + g;
#pragma unroll
    for (int ni = 0; ni < 16; ni++) {
        int col = h * 128 + ni * 8 + 2 * c;
        *reinterpret_cast<float2*>(&AO[(size_t)orow * 1024 + col]) =
            make_float2(o[ni][0] * inv0, o[ni][1] * inv0);
        *reinterpret_cast<float2*>(&AO[(size_t)(orow + 8) * 1024 + col]) =
            make_float2(o[ni][2] * inv1, o[ni][3] * inv1);
    }
}

// ---------------------------------------------------------------------------
extern "C" void kernel_launch(void* const* d_in, const int* in_sizes, int n_in,
                              void* d_out, int out_size) {
    const float* hs = (const float*)d_in[0];
    const float* Wq = (const float*)d_in[1];
    const float* Wk = (const float*)d_in[2];
    const float* Wv = (const float*)d_in[3];
    const float* Wo = (const float*)d_in[4];
    float* out = (float*)d_out;

    float *Qp, *Kp, *Vp, *AOp;
    uint32_t *WtQ, *WtK, *WtV, *WtO;
    cudaGetSymbolAddress((void**)&Qp,  g_Q);
    cudaGetSymbolAddress((void**)&Kp,  g_K);
    cudaGetSymbolAddress((void**)&Vp,  g_V);
    cudaGetSymbolAddress((void**)&AOp, g_AO);
    cudaGetSymbolAddress((void**)&WtQ, g_WtQ);
    cudaGetSymbolAddress((void**)&WtK, g_WtK);
    cudaGetSymbolAddress((void**)&WtV, g_WtV);
    cudaGetSymbolAddress((void**)&WtO, g_WtO);

    cudaFuncSetAttribute(attn_mma, cudaFuncAttributeMaxDynamicSharedMemorySize,
                         ATTN2_SMEM_BYTES);

    dim3 t32(32, 8);
    transpose_tf32<<<dim3(1024 / 32, 1024 / 32), t32>>>(Wq, WtQ, 1024, 1024);
    transpose_tf32<<<dim3(512  / 32, 1024 / 32), t32>>>(Wk, WtK, 1024, 512);
    transpose_tf32<<<dim3(512  / 32, 1024 / 32), t32>>>(Wv, WtV, 1024, 512);
    transpose_tf32<<<dim3(1024 / 32, 1024 / 32), t32>>>(Wo, WtO, 1024, 1024);

    // Projections (tf32 mma.sync)
    tf32_gemm<<<dim3(1024 / 128, BT / 128), 256>>>(hs, WtQ, Qp, 1024, 1024);
    tf32_gemm<<<dim3(512  / 128, BT / 128), 256>>>(hs, WtK, Kp, 512, 1024);
    tf32_gemm<<<dim3(512  / 128, BT / 128), 256>>>(hs, WtV, Vp, 512, 1024);

    // RoPE on Q and K
    {
        int totq = BT * NHQ * 64;
        int totk = BT * NKVH * 64;
        rope_kernel<<<(totq + 255) / 256, 256>>>(Qp, NHQ,  totq);
        rope_kernel<<<(totk + 255) / 256, 256>>>(Kp, NKVH, totk);
    }

    // Attention (tensorized)
    attn_mma<<<dim3(TSEQ / 128, 16 * NHQ), 256, ATTN2_SMEM_BYTES>>>(Qp, Kp, Vp, AOp);

    // Output projection
    tf32_gemm<<<dim3(1024 / 128, BT / 128), 256>>>(AOp, WtO, out, 1024, 1024);
}

// round 9
// speedup vs baseline: 3.3437x; 1.0753x over previous
#include <cuda_runtime.h>
#include <math.h>
#include <stdint.h>

// Problem constants
#define BT    8192     // B*T
#define TSEQ  512
#define NHQ   8
#define NKVH  4
#define DH    128

// Scratch (device globals: allocation-free contract)
__device__ float    g_Q  [BT * 1024];
__device__ float    g_K  [BT * 512];
__device__ float    g_V  [BT * 512];
__device__ uint32_t g_hst[BT * 1024];     // tf32(hidden_states)
__device__ uint32_t g_AOt[BT * 1024];     // tf32(attention out)
__device__ uint32_t g_WtQ[1024 * 1024];   // Wq^T  [N][K] tf32 bits
__device__ uint32_t g_WtK[512  * 1024];
__device__ uint32_t g_WtV[512  * 1024];
__device__ uint32_t g_WtO[1024 * 1024];

__device__ __forceinline__ uint32_t smem_u32(const void* p) {
    uint32_t r;
    asm("{ .reg .u64 t; cvta.to.shared.u64 t, %1; cvt.u32.u64 %0, t; }"
        : "=r"(r) : "l"(p));
    return r;
}
__device__ __forceinline__ uint32_t f2tf32(float f) {
    uint32_t r;
    asm("cvt.rna.tf32.f32 %0, %1;" : "=r"(r) : "f"(f));
    return r;
}
__device__ __forceinline__ void mma_tf32(float* c, const uint32_t* a,
                                         uint32_t b0, uint32_t b1) {
    asm volatile(
        "mma.sync.aligned.m16n8k8.row.col.f32.tf32.tf32.f32 "
        "{%0,%1,%2,%3}, {%4,%5,%6,%7}, {%8,%9}, {%0,%1,%2,%3};"
        : "+f"(c[0]), "+f"(c[1]), "+f"(c[2]), "+f"(c[3])
        : "r"(a[0]), "r"(a[1]), "r"(a[2]), "r"(a[3]), "r"(b0), "r"(b1));
}
__device__ __forceinline__ void cp16(uint32_t saddr, const void* gaddr) {
    asm volatile("cp.async.cg.shared.global [%0], [%1], 16;"
                 :: "r"(saddr), "l"(gaddr) : "memory");
}

// ---------------------------------------------------------------------------
// fp32 -> tf32 bits (RNA), vectorized
// ---------------------------------------------------------------------------
__global__ void to_tf32(const float* __restrict__ X, uint32_t* __restrict__ Y, int n4) {
    int i = blockIdx.x * blockDim.x + threadIdx.x;
    if (i >= n4) return;
    float4 v = reinterpret_cast<const float4*>(X)[i];
    uint4 r;
    r.x = f2tf32(v.x); r.y = f2tf32(v.y);
    r.z = f2tf32(v.z); r.w = f2tf32(v.w);
    reinterpret_cast<uint4*>(Y)[i] = r;
}

// ---------------------------------------------------------------------------
// Weight transpose + tf32 convert: W[K,N] fp32 -> Wt[N,K] tf32 bits
// ---------------------------------------------------------------------------
__global__ void transpose_tf32(const float* __restrict__ W, uint32_t* __restrict__ Wt,
                               int K, int N) {
    __shared__ float tile[32][33];
    int bx = blockIdx.x * 32;
    int by = blockIdx.y * 32;
    int tx = threadIdx.x, ty = threadIdx.y;
#pragma unroll
    for (int i = 0; i < 32; i += 8)
        tile[ty + i][tx] = W[(size_t)(by + ty + i) * N + bx + tx];
    __syncthreads();
#pragma unroll
    for (int i = 0; i < 32; i += 8)
        Wt[(size_t)(bx + ty + i) * K + by + tx] = f2tf32(tile[tx][ty + i]);
}

// ---------------------------------------------------------------------------
// tf32 mma.sync GEMM, cp.async 3-stage pipeline. All inputs tf32 bits, K-major.
// C[M,N] = A[M,K] @ Bt[N,K]^T. 128x128 tile, BK=32, 256 threads.
// ---------------------------------------------------------------------------
#define LDSS 36
#define GSTAGE 3
#define GEMM_STAGE_WORDS (128 * LDSS)
#define GEMM_SMEM_BYTES (2 * GSTAGE * GEMM_STAGE_WORDS * 4)   // 110592

__global__ __launch_bounds__(256, 2) void tf32_gemm(const uint32_t* __restrict__ A,
                                                    const uint32_t* __restrict__ Bt,
                                                    float* __restrict__ C,
                                                    int N, int K) {
    extern __shared__ uint32_t gsm[];
    uint32_t* As = gsm;                               // [GSTAGE][128*36]
    uint32_t* Bs = gsm + GSTAGE * GEMM_STAGE_WORDS;

    const int t    = threadIdx.x;
    const int lane = t & 31;
    const int wid  = t >> 5;
    const int warp_m = wid & 3;
    const int warp_n = wid >> 2;
    const int row0 = blockIdx.y * 128;
    const int col0 = blockIdx.x * 128;
    const int r_ = t >> 3;      // 0..31
    const int c4 = t & 7;       // 16B chunk within 32-word K tile
    const int ar_ = lane >> 2, ak = lane & 3;
    const int nkt = K >> 5;

    float acc[2][8][4];
#pragma unroll
    for (int mi = 0; mi < 2; mi++)
#pragma unroll
        for (int ni = 0; ni < 8; ni++)
#pragma unroll
            for (int x = 0; x < 4; x++) acc[mi][ni][x] = 0.f;

    auto ISSUE = [&](int kt) {
        if (kt < nkt) {
            int s = kt % GSTAGE;
            uint32_t* as = As + s * GEMM_STAGE_WORDS;
            uint32_t* bs = Bs + s * GEMM_STAGE_WORDS;
#pragma unroll
            for (int j = 0; j < 4; j++) {
                int r = r_ + j * 32;
                cp16(smem_u32(&as[r * LDSS + c4 * 4]),
                     &A[(size_t)(row0 + r) * K + kt * 32 + c4 * 4]);
                cp16(smem_u32(&bs[r * LDSS + c4 * 4]),
                     &Bt[(size_t)(col0 + r) * K + kt * 32 + c4 * 4]);
            }
        }
        asm volatile("cp.async.commit_group;" ::: "memory");
    };

    ISSUE(0);
    ISSUE(1);
    for (int kt = 0; kt < nkt; kt++) {
        asm volatile("cp.async.wait_group 1;" ::: "memory");
        __syncthreads();
        ISSUE(kt + 2);   // writes buffer (kt-1)%3: consumed at kt-1, freed by barrier

        const uint32_t* as = As + (kt % GSTAGE) * GEMM_STAGE_WORDS;
        const uint32_t* bs = Bs + (kt % GSTAGE) * GEMM_STAGE_WORDS;
#pragma unroll
        for (int ks = 0; ks < 4; ks++) {
            const int kc = ks * 8;
            uint32_t a[2][4];
#pragma unroll
            for (int mi = 0; mi < 2; mi++) {
                int rb = warp_m * 32 + mi * 16 + ar_;
                a[mi][0] = as[rb * LDSS + kc + ak];
                a[mi][1] = as[(rb + 8) * LDSS + kc + ak];
                a[mi][2] = as[rb * LDSS + kc + 4 + ak];
                a[mi][3] = as[(rb + 8) * LDSS + kc + 4 + ak];
            }
#pragma unroll
            for (int ni = 0; ni < 8; ni++) {
                int cb = (warp_n * 64 + ni * 8 + ar_) * LDSS + kc + ak;
                uint32_t b0 = bs[cb];
                uint32_t b1 = bs[cb + 4];
                mma_tf32(acc[0][ni], a[0], b0, b1);
                mma_tf32(acc[1][ni], a[1], b0, b1);
            }
        }
    }

#pragma unroll
    for (int mi = 0; mi < 2; mi++) {
        int rb = row0 + warp_m * 32 + mi * 16 + (lane >> 2);
#pragma unroll
        for (int ni = 0; ni < 8; ni++) {
            int cb = col0 + warp_n * 64 + ni * 8 + 2 * (lane & 3);
            *reinterpret_cast<float2*>(&C[(size_t)rb * N + cb]) =
                make_float2(acc[mi][ni][0], acc[mi][ni][1]);
            *reinterpret_cast<float2*>(&C[(size_t)(rb + 8) * N + cb]) =
                make_float2(acc[mi][ni][2], acc[mi][ni][3]);
        }
    }
}

// ---------------------------------------------------------------------------
// RoPE, in place on X[BT, nh*128].
// ---------------------------------------------------------------------------
__global__ void rope_kernel(float* __restrict__ X, int nh, int total) {
    int idx = blockIdx.x * blockDim.x + threadIdx.x;
    if (idx >= total) return;
    int i   = idx & 63;
    int h   = (idx >> 6) % nh;
    int row = idx / (nh * 64);
    int tpos = row & (TSEQ - 1);
    float inv = powf(10000.0f, -(float)i * (1.0f / 64.0f));
    float ang = (float)tpos * inv;
    float s, c;
    sincosf(ang, &s, &c);
    size_t base = (size_t)row * (nh * 128) + h * 128 + i;
    float x1 = X[base];
    float x2 = X[base + 64];
    X[base]      = x1 * c - x2 * s;
    X[base + 64] = x2 * c + x1 * s;
}

// ---------------------------------------------------------------------------
// Tensorized flash attention (tf32 mma.sync), causal, GQA.
// Epilogue now writes tf32 bits (RNA) straight into g_AOt for the Wo GEMM.
// ---------------------------------------------------------------------------
#define QK_LDS 132
#define AP_LDS 68
#define ATTN2_SMEM_WORDS (128 * QK_LDS + 64 * QK_LDS + 16 * 64 * 8 + 128 * AP_LDS)
#define ATTN2_SMEM_BYTES (ATTN2_SMEM_WORDS * 4)

__global__ __launch_bounds__(256) void attn_mma(const float* __restrict__ Q,
                                                const float* __restrict__ K,
                                                const float* __restrict__ V,
                                                uint32_t* __restrict__ AOt) {
    extern __shared__ uint32_t sm[];
    uint32_t* Qs = sm;                              // [128][132]
    uint32_t* Ks = Qs + 128 * QK_LDS;               // [64][132]
    uint32_t* Vs = Ks + 64 * QK_LDS;                // [16][64][8]
    uint32_t* Ps = Vs + 16 * 64 * 8;                // [128][68]

    const int t    = threadIdx.x;
    const int lane = t & 31;
    const int w    = t >> 5;
    const int qb   = 3 - blockIdx.x;                // heavy blocks first
    const int bh   = blockIdx.y;
    const int b    = bh >> 3;
    const int h    = bh & 7;
    const int kvh  = h >> 1;
    const int qrow0 = b * TSEQ + qb * 128;
    const int g = lane >> 2, c = lane & 3;
    const float scale = 0.08838834764831845f;

    // Load Q tile (128 rows x 128 d) -> Qs (tf32)
#pragma unroll
    for (int j = 0; j < 16; j++) {
        int fid = j * 256 + t;
        int r   = fid >> 5;
        int d0  = (fid & 31) * 4;
        float4 v = *reinterpret_cast<const float4*>(
            &Q[(size_t)(qrow0 + r) * 1024 + h * 128 + d0]);
        int base = r * QK_LDS + d0;
        Qs[base + 0] = f2tf32(v.x);
        Qs[base + 1] = f2tf32(v.y);
        Qs[base + 2] = f2tf32(v.z);
        Qs[base + 3] = f2tf32(v.w);
    }

    float o[16][4];
#pragma unroll
    for (int ni = 0; ni < 16; ni++)
#pragma unroll
        for (int x = 0; x < 4; x++) o[ni][x] = 0.f;
    float m_i[2] = {-1e30f, -1e30f};
    float l_i[2] = {0.f, 0.f};

    const int nkt = 2 * qb + 2;
    for (int kt = 0; kt < nkt; kt++) {
        __syncthreads();
        const int krow0 = b * TSEQ + kt * 64;
#pragma unroll
        for (int j = 0; j < 8; j++) {
            int fid = j * 256 + t;
            int r   = fid >> 5;
            int d0  = (fid & 31) * 4;
            float4 kv = *reinterpret_cast<const float4*>(
                &K[(size_t)(krow0 + r) * 512 + kvh * 128 + d0]);
            int base = r * QK_LDS + d0;
            Ks[base + 0] = f2tf32(kv.x);
            Ks[base + 1] = f2tf32(kv.y);
            Ks[base + 2] = f2tf32(kv.z);
            Ks[base + 3] = f2tf32(kv.w);
            float4 vv = *reinterpret_cast<const float4*>(
                &V[(size_t)(krow0 + r) * 512 + kvh * 128 + d0]);
            uint32_t* vp = &Vs[(d0 >> 3) * 512 + r * 8 + (d0 & 7)];
            vp[0] = f2tf32(vv.x);
            vp[1] = f2tf32(vv.y);
            vp[2] = f2tf32(vv.z);
            vp[3] = f2tf32(vv.w);
        }
        __syncthreads();

        // S = Q K^T
        float sacc[8][4];
#pragma unroll
        for (int ni = 0; ni < 8; ni++)
#pragma unroll
            for (int x = 0; x < 4; x++) sacc[ni][x] = 0.f;

#pragma unroll
        for (int ks = 0; ks < 16; ks++) {
            const int kc = ks * 8;
            uint32_t a[4];
            int abase = (w * 16 + g) * QK_LDS + kc + c;
            a[0] = Qs[abase];
            a[1] = Qs[abase + 8 * QK_LDS];
            a[2] = Qs[abase + 4];
            a[3] = Qs[abase + 8 * QK_LDS + 4];
#pragma unroll
            for (int ni = 0; ni < 8; ni++) {
                int bb = (ni * 8 + g) * QK_LDS + kc + c;
                mma_tf32(sacc[ni], a, Ks[bb], Ks[bb + 4]);
            }
        }

        // online softmax
        const int row0 = qb * 128 + w * 16 + g;
        const bool diag = (kt >= 2 * qb);
        float rmax0 = -1e30f, rmax1 = -1e30f;
#pragma unroll
        for (int ni = 0; ni < 8; ni++) {
#pragma unroll
            for (int x = 0; x < 4; x++) {
                float sv = sacc[ni][x] * scale;
                if (diag) {
                    int col = kt * 64 + ni * 8 + 2 * c + (x & 1);
                    int row = row0 + ((x >= 2) ? 8 : 0);
                    if (col > row) sv = -1e30f;
                }
                sacc[ni][x] = sv;
                if (x < 2) rmax0 = fmaxf(rmax0, sv);
                else       rmax1 = fmaxf(rmax1, sv);
            }
        }
#pragma unroll
        for (int off = 1; off < 4; off <<= 1) {
            rmax0 = fmaxf(rmax0, __shfl_xor_sync(0xffffffffu, rmax0, off));
            rmax1 = fmaxf(rmax1, __shfl_xor_sync(0xffffffffu, rmax1, off));
        }
        float mn0 = fmaxf(m_i[0], rmax0);
        float mn1 = fmaxf(m_i[1], rmax1);
        float corr0 = __expf(m_i[0] - mn0);
        float corr1 = __expf(m_i[1] - mn1);
        float rsum0 = 0.f, rsum1 = 0.f;
#pragma unroll
        for (int ni = 0; ni < 8; ni++) {
            float p0 = __expf(sacc[ni][0] - mn0);
            float p1 = __expf(sacc[ni][1] - mn0);
            float p2 = __expf(sacc[ni][2] - mn1);
            float p3 = __expf(sacc[ni][3] - mn1);
            sacc[ni][0] = p0; sacc[ni][1] = p1;
            sacc[ni][2] = p2; sacc[ni][3] = p3;
            rsum0 += p0 + p1;
            rsum1 += p2 + p3;
        }
#pragma unroll
        for (int off = 1; off < 4; off <<= 1) {
            rsum0 += __shfl_xor_sync(0xffffffffu, rsum0, off);
            rsum1 += __shfl_xor_sync(0xffffffffu, rsum1, off);
        }
        l_i[0] = l_i[0] * corr0 + rsum0;
        l_i[1] = l_i[1] * corr1 + rsum1;
        m_i[0] = mn0;
        m_i[1] = mn1;
#pragma unroll
        for (int ni = 0; ni < 16; ni++) {
            o[ni][0] *= corr0; o[ni][1] *= corr0;
            o[ni][2] *= corr1; o[ni][3] *= corr1;
        }

        // P -> smem (tf32), warp-private rows
#pragma unroll
        for (int ni = 0; ni < 8; ni++) {
            int p0 = (w * 16 + g) * AP_LDS + ni * 8 + 2 * c;
            Ps[p0]     = f2tf32(sacc[ni][0]);
            Ps[p0 + 1] = f2tf32(sacc[ni][1]);
            int p1 = p0 + 8 * AP_LDS;
            Ps[p1]     = f2tf32(sacc[ni][2]);
            Ps[p1 + 1] = f2tf32(sacc[ni][3]);
        }
        __syncwarp();

        // O += P V
#pragma unroll
        for (int kc2 = 0; kc2 < 8; kc2++) {
            const int koff = kc2 * 8;
            uint32_t a[4];
            int abase = (w * 16 + g) * AP_LDS + koff + c;
            a[0] = Ps[abase];
            a[1] = Ps[abase + 8 * AP_LDS];
            a[2] = Ps[abase + 4];
            a[3] = Ps[abase + 8 * AP_LDS + 4];
#pragma unroll
            for (int ni = 0; ni < 16; ni++) {
                int vb = ni * 512 + (koff + c) * 8 + g;
                mma_tf32(o[ni], a, Vs[vb], Vs[vb + 32]);
            }
        }
    }

    // epilogue: write tf32 bits for the Wo GEMM
    float inv0 = 1.0f / l_i[0];
    float inv1 = 1.0f / l_i[1];
    const int orow = qrow0 + w * 16 + g;
#pragma unroll
    for (int ni = 0; ni < 16; ni++) {
        int col = h * 128 + ni * 8 + 2 * c;
        uint2 v0, v1;
        v0.x = f2tf32(o[ni][0] * inv0);
        v0.y = f2tf32(o[ni][1] * inv0);
        v1.x = f2tf32(o[ni][2] * inv1);
        v1.y = f2tf32(o[ni][3] * inv1);
        *reinterpret_cast<uint2*>(&AOt[(size_t)orow * 1024 + col])       = v0;
        *reinterpret_cast<uint2*>(&AOt[(size_t)(orow + 8) * 1024 + col]) = v1;
    }
}

// ---------------------------------------------------------------------------
extern "C" void kernel_launch(void* const* d_in, const int* in_sizes, int n_in,
                              void* d_out, int out_size) {
    const float* hs = (const float*)d_in[0];
    const float* Wq = (const float*)d_in[1];
    const float* Wk = (const float*)d_in[2];
    const float* Wv = (const float*)d_in[3];
    const float* Wo = (const float*)d_in[4];
    float* out = (float*)d_out;

    float *Qp, *Kp, *Vp;
    uint32_t *hst, *AOt, *WtQ, *WtK, *WtV, *WtO;
    cudaGetSymbolAddress((void**)&Qp,  g_Q);
    cudaGetSymbolAddress((void**)&Kp,  g_K);
    cudaGetSymbolAddress((void**)&Vp,  g_V);
    cudaGetSymbolAddress((void**)&hst, g_hst);
    cudaGetSymbolAddress((void**)&AOt, g_AOt);
    cudaGetSymbolAddress((void**)&WtQ, g_WtQ);
    cudaGetSymbolAddress((void**)&WtK, g_WtK);
    cudaGetSymbolAddress((void**)&WtV, g_WtV);
    cudaGetSymbolAddress((void**)&WtO, g_WtO);

    cudaFuncSetAttribute(attn_mma, cudaFuncAttributeMaxDynamicSharedMemorySize,
                         ATTN2_SMEM_BYTES);
    cudaFuncSetAttribute(tf32_gemm, cudaFuncAttributeMaxDynamicSharedMemorySize,
                         GEMM_SMEM_BYTES);

    // Input conversions
    to_tf32<<<(BT * 1024 / 4 + 255) / 256, 256>>>(hs, hst, BT * 1024 / 4);
    dim3 t32(32, 8);
    transpose_tf32<<<dim3(1024 / 32, 1024 / 32), t32>>>(Wq, WtQ, 1024, 1024);
    transpose_tf32<<<dim3(512  / 32, 1024 / 32), t32>>>(Wk, WtK, 1024, 512);
    transpose_tf32<<<dim3(512  / 32, 1024 / 32), t32>>>(Wv, WtV, 1024, 512);
    transpose_tf32<<<dim3(1024 / 32, 1024 / 32), t32>>>(Wo, WtO, 1024, 1024);

    // Projections (tf32 mma.sync, cp.async pipeline)
    tf32_gemm<<<dim3(1024 / 128, BT / 128), 256, GEMM_SMEM_BYTES>>>(hst, WtQ, Qp, 1024, 1024);
    tf32_gemm<<<dim3(512  / 128, BT / 128), 256, GEMM_SMEM_BYTES>>>(hst, WtK, Kp, 512, 1024);
    tf32_gemm<<<dim3(512  / 128, BT / 128), 256, GEMM_SMEM_BYTES>>>(hst, WtV, Vp, 512, 1024);

    // RoPE on Q and K
    {
        int totq = BT * NHQ * 64;
        int totk = BT * NKVH * 64;
        rope_kernel<<<(totq + 255) / 256, 256>>>(Qp, NHQ,  totq);
        rope_kernel<<<(totk + 255) / 256, 256>>>(Kp, NKVH, totk);
    }

    // Attention (tensorized) -> tf32 bits
    attn_mma<<<dim3(TSEQ / 128, 16 * NHQ), 256, ATTN2_SMEM_BYTES>>>(Qp, Kp, Vp, AOt);

    // Output projection
    tf32_gemm<<<dim3(1024 / 128, BT / 128), 256, GEMM_SMEM_BYTES>>>(AOt, WtO, out, 1024, 1024);
}

// round 12
// speedup vs baseline: 3.6730x; 1.0985x over previous
#include <cuda_runtime.h>
#include <math.h>
#include <stdint.h>

// Problem constants
#define BT    8192     // B*T
#define TSEQ  512
#define NHQ   8
#define NKVH  4
#define DH    128

// Scratch (device globals: allocation-free contract)
__device__ float    g_QKV [BT * 2048];       // Q|K|V per row (fp32)
__device__ uint32_t g_hst [BT * 1024];       // tf32(hidden_states)
__device__ uint32_t g_AOt [BT * 1024];       // tf32(attention out)
__device__ uint32_t g_WtQKV[2048 * 1024];    // [WqT;WkT;WvT] [N][K] tf32 bits
__device__ uint32_t g_WtO [1024 * 1024];     // WoT
__device__ float    g_cos [TSEQ * 64];
__device__ float    g_sin [TSEQ * 64];

__device__ __forceinline__ uint32_t smem_u32(const void* p) {
    uint32_t r;
    asm("{ .reg .u64 t; cvta.to.shared.u64 t, %1; cvt.u32.u64 %0, t; }"
        : "=r"(r) : "l"(p));
    return r;
}
__device__ __forceinline__ uint32_t f2tf32(float f) {
    uint32_t r;
    asm("cvt.rna.tf32.f32 %0, %1;" : "=r"(r) : "f"(f));
    return r;
}
__device__ __forceinline__ void mma_tf32(float* c, const uint32_t* a,
                                         uint32_t b0, uint32_t b1) {
    asm volatile(
        "mma.sync.aligned.m16n8k8.row.col.f32.tf32.tf32.f32 "
        "{%0,%1,%2,%3}, {%4,%5,%6,%7}, {%8,%9}, {%0,%1,%2,%3};"
        : "+f"(c[0]), "+f"(c[1]), "+f"(c[2]), "+f"(c[3])
        : "r"(a[0]), "r"(a[1]), "r"(a[2]), "r"(a[3]), "r"(b0), "r"(b1));
}
__device__ __forceinline__ void cp16(uint32_t saddr, const void* gaddr) {
    asm volatile("cp.async.cg.shared.global [%0], [%1], 16;"
                 :: "r"(saddr), "l"(gaddr) : "memory");
}

// ---------------------------------------------------------------------------
// fp32 -> tf32 bits (RNA), vectorized
// ---------------------------------------------------------------------------
__global__ void to_tf32(const float* __restrict__ X, uint32_t* __restrict__ Y, int n4) {
    int i = blockIdx.x * blockDim.x + threadIdx.x;
    if (i >= n4) return;
    float4 v = reinterpret_cast<const float4*>(X)[i];
    uint4 r;
    r.x = f2tf32(v.x); r.y = f2tf32(v.y);
    r.z = f2tf32(v.z); r.w = f2tf32(v.w);
    reinterpret_cast<uint4*>(Y)[i] = r;
}

// ---------------------------------------------------------------------------
// RoPE cos/sin table: [tpos][i], i<64
// ---------------------------------------------------------------------------
__global__ void rope_table() {
    int tpos = blockIdx.x;
    int i    = threadIdx.x;
    float inv = powf(10000.0f, -(float)i * (1.0f / 64.0f));
    float s, c;
    sincosf((float)tpos * inv, &s, &c);
    g_cos[tpos * 64 + i] = c;
    g_sin[tpos * 64 + i] = s;
}

// ---------------------------------------------------------------------------
// Weight transpose + tf32 convert: W[K,N] fp32 -> Wt[N,K] tf32 bits
// ---------------------------------------------------------------------------
__global__ void transpose_tf32(const float* __restrict__ W, uint32_t* __restrict__ Wt,
                               int K, int N) {
    __shared__ float tile[32][33];
    int bx = blockIdx.x * 32;
    int by = blockIdx.y * 32;
    int tx = threadIdx.x, ty = threadIdx.y;
#pragma unroll
    for (int i = 0; i < 32; i += 8)
        tile[ty + i][tx] = W[(size_t)(by + ty + i) * N + bx + tx];
    __syncthreads();
#pragma unroll
    for (int i = 0; i < 32; i += 8)
        Wt[(size_t)(bx + ty + i) * K + by + tx] = f2tf32(tile[tx][ty + i]);
}

// ---------------------------------------------------------------------------
// tf32 mma.sync GEMM, cp.async 3-stage pipeline. All inputs tf32 bits, K-major.
// C[M,N] = A[M,K] @ Bt[N,K]^T. 128x128 tile, BK=32, 256 threads.
// ---------------------------------------------------------------------------
#define LDSS 36
#define GSTAGE 3
#define GEMM_STAGE_WORDS (128 * LDSS)
#define GEMM_SMEM_BYTES (2 * GSTAGE * GEMM_STAGE_WORDS * 4)   // 110592

__global__ __launch_bounds__(256, 2) void tf32_gemm(const uint32_t* __restrict__ A,
                                                    const uint32_t* __restrict__ Bt,
                                                    float* __restrict__ C,
                                                    int N, int K) {
    extern __shared__ uint32_t gsm[];
    uint32_t* As = gsm;                               // [GSTAGE][128*36]
    uint32_t* Bs = gsm + GSTAGE * GEMM_STAGE_WORDS;

    const int t    = threadIdx.x;
    const int lane = t & 31;
    const int wid  = t >> 5;
    const int warp_m = wid & 3;
    const int warp_n = wid >> 2;
    const int row0 = blockIdx.y * 128;
    const int col0 = blockIdx.x * 128;
    const int r_ = t >> 3;      // 0..31
    const int c4 = t & 7;       // 16B chunk within 32-word K tile
    const int ar_ = lane >> 2, ak = lane & 3;
    const int nkt = K >> 5;

    float acc[2][8][4];
#pragma unroll
    for (int mi = 0; mi < 2; mi++)
#pragma unroll
        for (int ni = 0; ni < 8; ni++)
#pragma unroll
            for (int x = 0; x < 4; x++) acc[mi][ni][x] = 0.f;

    auto ISSUE = [&](int kt) {
        if (kt < nkt) {
            int s = kt % GSTAGE;
            uint32_t* as = As + s * GEMM_STAGE_WORDS;
            uint32_t* bs = Bs + s * GEMM_STAGE_WORDS;
#pragma unroll
            for (int j = 0; j < 4; j++) {
                int r = r_ + j * 32;
                cp16(smem_u32(&as[r * LDSS + c4 * 4]),
                     &A[(size_t)(row0 + r) * K + kt * 32 + c4 * 4]);
                cp16(smem_u32(&bs[r * LDSS + c4 * 4]),
                     &Bt[(size_t)(col0 + r) * K + kt * 32 + c4 * 4]);
            }
        }
        asm volatile("cp.async.commit_group;" ::: "memory");
    };

    ISSUE(0);
    ISSUE(1);
    for (int kt = 0; kt < nkt; kt++) {
        asm volatile("cp.async.wait_group 1;" ::: "memory");
        __syncthreads();
        ISSUE(kt + 2);   // writes buffer (kt-1)%3: consumed at kt-1, freed by barrier

        const uint32_t* as = As + (kt % GSTAGE) * GEMM_STAGE_WORDS;
        const uint32_t* bs = Bs + (kt % GSTAGE) * GEMM_STAGE_WORDS;
#pragma unroll
        for (int ks = 0; ks < 4; ks++) {
            const int kc = ks * 8;
            uint32_t a[2][4];
#pragma unroll
            for (int mi = 0; mi < 2; mi++) {
                int rb = warp_m * 32 + mi * 16 + ar_;
                a[mi][0] = as[rb * LDSS + kc + ak];
                a[mi][1] = as[(rb + 8) * LDSS + kc + ak];
                a[mi][2] = as[rb * LDSS + kc + 4 + ak];
                a[mi][3] = as[(rb + 8) * LDSS + kc + 4 + ak];
            }
#pragma unroll
            for (int ni = 0; ni < 8; ni++) {
                int cb = (warp_n * 64 + ni * 8 + ar_) * LDSS + kc + ak;
                uint32_t b0 = bs[cb];
                uint32_t b1 = bs[cb + 4];
                mma_tf32(acc[0][ni], a[0], b0, b1);
                mma_tf32(acc[1][ni], a[1], b0, b1);
            }
        }
    }

#pragma unroll
    for (int mi = 0; mi < 2; mi++) {
        int rb = row0 + warp_m * 32 + mi * 16 + (lane >> 2);
#pragma unroll
        for (int ni = 0; ni < 8; ni++) {
            int cb = col0 + warp_n * 64 + ni * 8 + 2 * (lane & 3);
            *reinterpret_cast<float2*>(&C[(size_t)rb * N + cb]) =
                make_float2(acc[mi][ni][0], acc[mi][ni][1]);
            *reinterpret_cast<float2*>(&C[(size_t)(rb + 8) * N + cb]) =
                make_float2(acc[mi][ni][2], acc[mi][ni][3]);
        }
    }
}

// ---------------------------------------------------------------------------
// Tensorized flash attention (tf32 mma.sync), causal, GQA, fused RoPE.
// QKV layout: row-major [BT][2048], Q at col h*128, K at 1024+kvh*128,
// V at 1536+kvh*128. RoPE applied in the Q/K smem loaders via g_cos/g_sin.
// Output written as tf32 bits to AOt.
// ---------------------------------------------------------------------------
#define QK_LDS 132
#define AP_LDS 68
#define ATTN2_SMEM_WORDS (128 * QK_LDS + 64 * QK_LDS + 16 * 64 * 8 + 128 * AP_LDS)
#define ATTN2_SMEM_BYTES (ATTN2_SMEM_WORDS * 4)

__global__ __launch_bounds__(256) void attn_mma(const float* __restrict__ QKV,
                                                uint32_t* __restrict__ AOt) {
    extern __shared__ uint32_t sm[];
    uint32_t* Qs = sm;                              // [128][132]
    uint32_t* Ks = Qs + 128 * QK_LDS;               // [64][132]
    uint32_t* Vs = Ks + 64 * QK_LDS;                // [16][64][8]
    uint32_t* Ps = Vs + 16 * 64 * 8;                // [128][68]

    const int t    = threadIdx.x;
    const int lane = t & 31;
    const int w    = t >> 5;
    const int qb   = 3 - blockIdx.x;                // heavy blocks first
    const int bh   = blockIdx.y;
    const int b    = bh >> 3;
    const int h    = bh & 7;
    const int kvh  = h >> 1;
    const int qrow0 = b * TSEQ + qb * 128;
    const int g = lane >> 2, c = lane & 3;
    const float scale = 0.08838834764831845f;

    // Load Q tile (128 rows x 128 d) with fused RoPE -> Qs (tf32)
#pragma unroll
    for (int j = 0; j < 8; j++) {
        int fid = j * 256 + t;
        int r   = fid >> 4;            // 0..127
        int hc  = (fid & 15) * 4;      // 0..60
        const float* qp = &QKV[(size_t)(qrow0 + r) * 2048 + h * 128 + hc];
        float4 x1 = *reinterpret_cast<const float4*>(qp);
        float4 x2 = *reinterpret_cast<const float4*>(qp + 64);
        int tpos = qb * 128 + r;
        float4 cs = *reinterpret_cast<const float4*>(&g_cos[tpos * 64 + hc]);
        float4 sn = *reinterpret_cast<const float4*>(&g_sin[tpos * 64 + hc]);
        int base = r * QK_LDS + hc;
        Qs[base + 0]  = f2tf32(x1.x * cs.x - x2.x * sn.x);
        Qs[base + 1]  = f2tf32(x1.y * cs.y - x2.y * sn.y);
        Qs[base + 2]  = f2tf32(x1.z * cs.z - x2.z * sn.z);
        Qs[base + 3]  = f2tf32(x1.w * cs.w - x2.w * sn.w);
        Qs[base + 64] = f2tf32(x2.x * cs.x + x1.x * sn.x);
        Qs[base + 65] = f2tf32(x2.y * cs.y + x1.y * sn.y);
        Qs[base + 66] = f2tf32(x2.z * cs.z + x1.z * sn.z);
        Qs[base + 67] = f2tf32(x2.w * cs.w + x1.w * sn.w);
    }

    float o[16][4];
#pragma unroll
    for (int ni = 0; ni < 16; ni++)
#pragma unroll
        for (int x = 0; x < 4; x++) o[ni][x] = 0.f;
    float m_i[2] = {-1e30f, -1e30f};
    float l_i[2] = {0.f, 0.f};

    const int nkt = 2 * qb + 2;
    for (int kt = 0; kt < nkt; kt++) {
        __syncthreads();
        const int krow0 = b * TSEQ + kt * 64;
        // K tile (64 x 128) with fused RoPE
#pragma unroll
        for (int j = 0; j < 4; j++) {
            int fid = j * 256 + t;
            int r   = fid >> 4;            // 0..63
            int hc  = (fid & 15) * 4;
            const float* kp = &QKV[(size_t)(krow0 + r) * 2048 + 1024 + kvh * 128 + hc];
            float4 x1 = *reinterpret_cast<const float4*>(kp);
            float4 x2 = *reinterpret_cast<const float4*>(kp + 64);
            int tpos = kt * 64 + r;
            float4 cs = *reinterpret_cast<const float4*>(&g_cos[tpos * 64 + hc]);
            float4 sn = *reinterpret_cast<const float4*>(&g_sin[tpos * 64 + hc]);
            int base = r * QK_LDS + hc;
            Ks[base + 0]  = f2tf32(x1.x * cs.x - x2.x * sn.x);
            Ks[base + 1]  = f2tf32(x1.y * cs.y - x2.y * sn.y);
            Ks[base + 2]  = f2tf32(x1.z * cs.z - x2.z * sn.z);
            Ks[base + 3]  = f2tf32(x1.w * cs.w - x2.w * sn.w);
            Ks[base + 64] = f2tf32(x2.x * cs.x + x1.x * sn.x);
            Ks[base + 65] = f2tf32(x2.y * cs.y + x1.y * sn.y);
            Ks[base + 66] = f2tf32(x2.z * cs.z + x1.z * sn.z);
            Ks[base + 67] = f2tf32(x2.w * cs.w + x1.w * sn.w);
        }
        // V tile (64 x 128), plain
#pragma unroll
        for (int j = 0; j < 8; j++) {
            int fid = j * 256 + t;
            int r   = fid >> 5;            // 0..63
            int d0  = (fid & 31) * 4;
            float4 vv = *reinterpret_cast<const float4*>(
                &QKV[(size_t)(krow0 + r) * 2048 + 1536 + kvh * 128 + d0]);
            uint32_t* vp = &Vs[(d0 >> 3) * 512 + r * 8 + (d0 & 7)];
            vp[0] = f2tf32(vv.x);
            vp[1] = f2tf32(vv.y);
            vp[2] = f2tf32(vv.z);
            vp[3] = f2tf32(vv.w);
        }
        __syncthreads();

        // S = Q K^T
        float sacc[8][4];
#pragma unroll
        for (int ni = 0; ni < 8; ni++)
#pragma unroll
            for (int x = 0; x < 4; x++) sacc[ni][x] = 0.f;

#pragma unroll
        for (int ks = 0; ks < 16; ks++) {
            const int kc = ks * 8;
            uint32_t a[4];
            int abase = (w * 16 + g) * QK_LDS + kc + c;
            a[0] = Qs[abase];
            a[1] = Qs[abase + 8 * QK_LDS];
            a[2] = Qs[abase + 4];
            a[3] = Qs[abase + 8 * QK_LDS + 4];
#pragma unroll
            for (int ni = 0; ni < 8; ni++) {
                int bb = (ni * 8 + g) * QK_LDS + kc + c;
                mma_tf32(sacc[ni], a, Ks[bb], Ks[bb + 4]);
            }
        }

        // online softmax
        const int row0 = qb * 128 + w * 16 + g;
        const bool diag = (kt >= 2 * qb);
        float rmax0 = -1e30f, rmax1 = -1e30f;
#pragma unroll
        for (int ni = 0; ni < 8; ni++) {
#pragma unroll
            for (int x = 0; x < 4; x++) {
                float sv = sacc[ni][x] * scale;
                if (diag) {
                    int col = kt * 64 + ni * 8 + 2 * c + (x & 1);
                    int row = row0 + ((x >= 2) ? 8 : 0);
                    if (col > row) sv = -1e30f;
                }
                sacc[ni][x] = sv;
                if (x < 2) rmax0 = fmaxf(rmax0, sv);
                else       rmax1 = fmaxf(rmax1, sv);
            }
        }
#pragma unroll
        for (int off = 1; off < 4; off <<= 1) {
            rmax0 = fmaxf(rmax0, __shfl_xor_sync(0xffffffffu, rmax0, off));
            rmax1 = fmaxf(rmax1, __shfl_xor_sync(0xffffffffu, rmax1, off));
        }
        float mn0 = fmaxf(m_i[0], rmax0);
        float mn1 = fmaxf(m_i[1], rmax1);
        float corr0 = __expf(m_i[0] - mn0);
        float corr1 = __expf(m_i[1] - mn1);
        float rsum0 = 0.f, rsum1 = 0.f;
#pragma unroll
        for (int ni = 0; ni < 8; ni++) {
            float p0 = __expf(sacc[ni][0] - mn0);
            float p1 = __expf(sacc[ni][1] - mn0);
            float p2 = __expf(sacc[ni][2] - mn1);
            float p3 = __expf(sacc[ni][3] - mn1);
            sacc[ni][0] = p0; sacc[ni][1] = p1;
            sacc[ni][2] = p2; sacc[ni][3] = p3;
            rsum0 += p0 + p1;
            rsum1 += p2 + p3;
        }
#pragma unroll
        for (int off = 1; off < 4; off <<= 1) {
            rsum0 += __shfl_xor_sync(0xffffffffu, rsum0, off);
            rsum1 += __shfl_xor_sync(0xffffffffu, rsum1, off);
        }
        l_i[0] = l_i[0] * corr0 + rsum0;
        l_i[1] = l_i[1] * corr1 + rsum1;
        m_i[0] = mn0;
        m_i[1] = mn1;
#pragma unroll
        for (int ni = 0; ni < 16; ni++) {
            o[ni][0] *= corr0; o[ni][1] *= corr0;
            o[ni][2] *= corr1; o[ni][3] *= corr1;
        }

        // P -> smem (tf32), warp-private rows
#pragma unroll
        for (int ni = 0; ni < 8; ni++) {
            int p0 = (w * 16 + g) * AP_LDS + ni * 8 + 2 * c;
            Ps[p0]     = f2tf32(sacc[ni][0]);
            Ps[p0 + 1] = f2tf32(sacc[ni][1]);
            int p1 = p0 + 8 * AP_LDS;
            Ps[p1]     = f2tf32(sacc[ni][2]);
            Ps[p1 + 1] = f2tf32(sacc[ni][3]);
        }
        __syncwarp();

        // O += P V
#pragma unroll
        for (int kc2 = 0; kc2 < 8; kc2++) {
            const int koff = kc2 * 8;
            uint32_t a[4];
            int abase = (w * 16 + g) * AP_LDS + koff + c;
            a[0] = Ps[abase];
            a[1] = Ps[abase + 8 * AP_LDS];
            a[2] = Ps[abase + 4];
            a[3] = Ps[abase + 8 * AP_LDS + 4];
#pragma unroll
            for (int ni = 0; ni < 16; ni++) {
                int vb = ni * 512 + (koff + c) * 8 + g;
                mma_tf32(o[ni], a, Vs[vb], Vs[vb + 32]);
            }
        }
    }

    // epilogue: write tf32 bits for the Wo GEMM
    float inv0 = 1.0f / l_i[0];
    float inv1 = 1.0f / l_i[1];
    const int orow = qrow0 + w * 16 + g;
#pragma unroll
    for (int ni = 0; ni < 16; ni++) {
        int col = h * 128 + ni * 8 + 2 * c;
        uint2 v0, v1;
        v0.x = f2tf32(o[ni][0] * inv0);
        v0.y = f2tf32(o[ni][1] * inv0);
        v1.x = f2tf32(o[ni][2] * inv1);
        v1.y = f2tf32(o[ni][3] * inv1);
        *reinterpret_cast<uint2*>(&AOt[(size_t)orow * 1024 + col])       = v0;
        *reinterpret_cast<uint2*>(&AOt[(size_t)(orow + 8) * 1024 + col]) = v1;
    }
}

// ---------------------------------------------------------------------------
extern "C" void kernel_launch(void* const* d_in, const int* in_sizes, int n_in,
                              void* d_out, int out_size) {
    const float* hs = (const float*)d_in[0];
    const float* Wq = (const float*)d_in[1];
    const float* Wk = (const float*)d_in[2];
    const float* Wv = (const float*)d_in[3];
    const float* Wo = (const float*)d_in[4];
    float* out = (float*)d_out;

    float *QKVp;
    uint32_t *hst, *AOt, *WtQKV, *WtO;
    cudaGetSymbolAddress((void**)&QKVp,  g_QKV);
    cudaGetSymbolAddress((void**)&hst,   g_hst);
    cudaGetSymbolAddress((void**)&AOt,   g_AOt);
    cudaGetSymbolAddress((void**)&WtQKV, g_WtQKV);
    cudaGetSymbolAddress((void**)&WtO,   g_WtO);

    cudaFuncSetAttribute(attn_mma, cudaFuncAttributeMaxDynamicSharedMemorySize,
                         ATTN2_SMEM_BYTES);
    cudaFuncSetAttribute(tf32_gemm, cudaFuncAttributeMaxDynamicSharedMemorySize,
                         GEMM_SMEM_BYTES);

    // Input conversions + RoPE table
    to_tf32<<<(BT * 1024 / 4 + 255) / 256, 256>>>(hs, hst, BT * 1024 / 4);
    rope_table<<<TSEQ, 64>>>();
    dim3 t32(32, 8);
    transpose_tf32<<<dim3(1024 / 32, 1024 / 32), t32>>>(Wq, WtQKV, 1024, 1024);
    transpose_tf32<<<dim3(512  / 32, 1024 / 32), t32>>>(Wk, WtQKV + 1024 * 1024, 1024, 512);
    transpose_tf32<<<dim3(512  / 32, 1024 / 32), t32>>>(Wv, WtQKV + 1536 * 1024, 1024, 512);
    transpose_tf32<<<dim3(1024 / 32, 1024 / 32), t32>>>(Wo, WtO, 1024, 1024);

    // Fused QKV projection (one GEMM, N=2048)
    tf32_gemm<<<dim3(2048 / 128, BT / 128), 256, GEMM_SMEM_BYTES>>>(hst, WtQKV, QKVp, 2048, 1024);

    // Attention (tensorized, fused RoPE) -> tf32 bits
    attn_mma<<<dim3(TSEQ / 128, 16 * NHQ), 256, ATTN2_SMEM_BYTES>>>(QKVp, AOt);

    // Output projection
    tf32_gemm<<<dim3(1024 / 128, BT / 128), 256, GEMM_SMEM_BYTES>>>(AOt, WtO, out, 1024, 1024);
}